// round 15
// baseline (speedup 1.0000x reference)
#include <cuda_runtime.h>
#include <cuda_fp16.h>
#include <cstdint>

#define Bq   8
#define Nn   1024
#define DIN  256
#define DOUT 256
#define Rr   4

// ------------------------- scratch globals ----------------------------------
__device__ __half g_xf[(size_t)Bq * Nn * DIN];
__device__ __half g_rwhf[(size_t)Rr * DOUT * DIN];
__device__ __half g_rwlf[(size_t)Rr * DOUT * DIN];
__device__ float  g_v[Rr * DIN];          // rel_w^T @ attn_w[d:]
__device__ float  g_c[Rr];                // rb . attn_w[d:]
__device__ float  g_w[Bq * Rr * Nn];
__device__ float  g_invZ[Bq * Rr * Nn];
__device__ __half g_wff[(size_t)Bq * Rr * DOUT * Nn];      // wf^T fp16 [br][d][m]
__device__ __half g_adjh[(size_t)Bq * Rr * Nn * Nn];       // 64 MB fp16 {0,1}

// ------------------------- helpers ------------------------------------------
__device__ __forceinline__ uint32_t smem_u32(const void* p) {
    uint32_t a;
    asm("{ .reg .u64 t; cvta.to.shared.u64 t, %1; cvt.u32.u64 %0, t; }"
        : "=r"(a) : "l"(p));
    return a;
}
#define CP_ASYNC16(dst, src) asm volatile("cp.async.cg.shared.global [%0], [%1], 16;" :: "r"(dst), "l"(src))
#define CP_COMMIT()          asm volatile("cp.async.commit_group;" ::: "memory")
#define CP_WAIT1()           asm volatile("cp.async.wait_group 1;" ::: "memory")
#define CP_WAIT0()           asm volatile("cp.async.wait_group 0;" ::: "memory")

__device__ __forceinline__ uint32_t sw128(uint32_t off) {
    return off ^ ((off >> 3) & 0x70);
}
__device__ __forceinline__ void ldsm4(uint32_t& r0, uint32_t& r1,
                                      uint32_t& r2, uint32_t& r3, uint32_t a) {
    asm volatile("ldmatrix.sync.aligned.m8n8.x4.shared.b16 {%0,%1,%2,%3}, [%4];"
                 : "=r"(r0), "=r"(r1), "=r"(r2), "=r"(r3) : "r"(a));
}
__device__ __forceinline__ void mma16816h(float* c, const uint32_t* a,
                                          const uint32_t* b) {
    asm volatile("mma.sync.aligned.m16n8k16.row.col.f32.f16.f16.f32 "
        "{%0,%1,%2,%3}, {%4,%5,%6,%7}, {%8,%9}, {%0,%1,%2,%3};"
        : "+f"(c[0]), "+f"(c[1]), "+f"(c[2]), "+f"(c[3])
        : "r"(a[0]), "r"(a[1]), "r"(a[2]), "r"(a[3]), "r"(b[0]), "r"(b[1]));
}
__device__ __forceinline__ void hsplit(float v, __half& h, __half& l) {
    h = __float2half_rn(v);
    l = __float2half_rn(v - __half2float(h));
}
__device__ __forceinline__ uint32_t pack_h2(__half a, __half b) {
    return (uint32_t)__half_as_ushort(a) | ((uint32_t)__half_as_ushort(b) << 16);
}

// ---------------------------------------------------------------------------
// merged conversions: blocks [0, XB) convert x; [XB, XB+WB) convert rel_w
// ---------------------------------------------------------------------------
#define XB ((Bq * Nn * DIN / 4) / 256)
#define WB ((Rr * DOUT * DIN / 4) / 256)
__global__ __launch_bounds__(256) void conv_kernel(const float* __restrict__ x,
                                                   const float* __restrict__ rw) {
    if (blockIdx.x < XB) {
        size_t i = (size_t)blockIdx.x * 256 + threadIdx.x;
        float4 v = ((const float4*)x)[i];
        uint2 H;
        H.x = pack_h2(__float2half_rn(v.x), __float2half_rn(v.y));
        H.y = pack_h2(__float2half_rn(v.z), __float2half_rn(v.w));
        *(uint2*)&g_xf[4 * i] = H;
    } else {
        size_t i = (size_t)(blockIdx.x - XB) * 256 + threadIdx.x;
        float4 v = ((const float4*)rw)[i];
        __half h0, h1, h2, h3, l0, l1, l2, l3;
        hsplit(v.x, h0, l0); hsplit(v.y, h1, l1);
        hsplit(v.z, h2, l2); hsplit(v.w, h3, l3);
        uint2 H, L;
        H.x = pack_h2(h0, h1); H.y = pack_h2(h2, h3);
        L.x = pack_h2(l0, l1); L.y = pack_h2(l2, l3);
        *(uint2*)&g_rwhf[4 * i] = H;
        *(uint2*)&g_rwlf[4 * i] = L;
    }
}

// ---------------------------------------------------------------------------
// vw: v[r,k] = sum_d awj[d] * rw[r,d,k];  c[r] = sum_d rb[r,d]*awj[d]
// 4 blocks (one per r), 256 threads (one per k)
// ---------------------------------------------------------------------------
__global__ __launch_bounds__(256) void vw_kernel(
    const float* __restrict__ rw, const float* __restrict__ rb,
    const float* __restrict__ aw)
{
    __shared__ float awjs[256];
    __shared__ float red[8];
    const int r = blockIdx.x, t = threadIdx.x, lane = t & 31;
    awjs[t] = aw[DOUT + t];
    __syncthreads();
    const float* base = rw + (size_t)r * DOUT * DIN;
    float v = 0.f;
    #pragma unroll 4
    for (int d = 0; d < DOUT; d++)
        v = fmaf(awjs[d], base[(size_t)d * DIN + t], v);
    g_v[r * DIN + t] = v;

    float c = rb[r * DOUT + t] * awjs[t];
    #pragma unroll
    for (int o = 16; o; o >>= 1) c += __shfl_xor_sync(0xffffffffu, c, o);
    if (lane == 0) red[t >> 5] = c;
    __syncthreads();
    if (t == 0) {
        float s = 0.f;
        #pragma unroll
        for (int i = 0; i < 8; i++) s += red[i];
        g_c[r] = s;
    }
}

// ---------------------------------------------------------------------------
// w: w[b,r,m] = exp(x[b,m,:] . v[r] + c[r])   (fp32; == feats . awj exactly)
// warp per (b,m) row, 4 relations at once. grid Bq*Nn/8, 256 threads.
// ---------------------------------------------------------------------------
__global__ __launch_bounds__(256) void w_kernel(const float* __restrict__ x) {
    __shared__ float vs[Rr][DIN];
    __shared__ float cs[Rr];
    const int t = threadIdx.x, wid = t >> 5, lane = t & 31;
    for (int i = t; i < Rr * DIN; i += 256) vs[i >> 8][i & 255] = g_v[i];
    if (t < Rr) cs[t] = g_c[t];
    __syncthreads();

    size_t row = (size_t)blockIdx.x * 8 + wid;   // (b, m)
    int b = (int)(row >> 10), m = (int)(row & 1023);
    const float* xr = x + ((size_t)b * Nn + m) * DIN;
    float a0 = 0.f, a1 = 0.f, a2 = 0.f, a3 = 0.f;
    #pragma unroll
    for (int k = lane; k < DIN; k += 32) {
        float xv = xr[k];
        a0 = fmaf(xv, vs[0][k], a0);
        a1 = fmaf(xv, vs[1][k], a1);
        a2 = fmaf(xv, vs[2][k], a2);
        a3 = fmaf(xv, vs[3][k], a3);
    }
    #pragma unroll
    for (int o = 16; o; o >>= 1) {
        a0 += __shfl_xor_sync(0xffffffffu, a0, o);
        a1 += __shfl_xor_sync(0xffffffffu, a1, o);
        a2 += __shfl_xor_sync(0xffffffffu, a2, o);
        a3 += __shfl_xor_sync(0xffffffffu, a3, o);
    }
    if (lane == 0) {
        g_w[((b * Rr + 0) << 10) + m] = __expf(a0 + cs[0]);
        g_w[((b * Rr + 1) << 10) + m] = __expf(a1 + cs[1]);
        g_w[((b * Rr + 2) << 10) + m] = __expf(a2 + cs[2]);
        g_w[((b * Rr + 3) << 10) + m] = __expf(a3 + cs[3]);
    }
}

// ---------------------------------------------------------------------------
// FUSED feats+wf kernel (2-term fp16). Epilogue now READS g_w (sj removed).
// ---------------------------------------------------------------------------
#define FW_SMEM (1024 + 2 * 81920)
__global__ __launch_bounds__(512, 1) void fw_kernel(const float* __restrict__ rb)
{
    extern __shared__ char smem[];
    __shared__ float rbs[256];
    __shared__ float wsm[128];
    char* abp = (char*)(((uintptr_t)smem + 1023) & ~(uintptr_t)1023);
    const uint32_t ab = (smem_u32(smem) + 1023) & ~1023u;
    const int tid = threadIdx.x, wid = tid >> 5, lane = tid & 31;
    const int n0 = blockIdx.x * 128;
    const int br = blockIdx.y, b = br >> 2, r = br & 3;
    const int wm = (wid >> 2) * 32, wn = (wid & 3) * 64;

    if (tid < 256) rbs[tid] = rb[r * DOUT + tid];
    if (tid >= 256 && tid < 384) wsm[tid - 256] = g_w[br * Nn + n0 + tid - 256];

    auto prefetch = [&](int c, int stage) {
        uint32_t base = ab + stage * 81920;
        for (int u = tid; u < 5120; u += 512) {
            uint32_t dst;
            const __half* src;
            if (u < 1024) {
                int row = u >> 3, un = u & 7;
                dst = base + sw128(row * 128 + un * 16);
                src = g_xf + (size_t)b * (Nn * DIN) + (size_t)(n0 + row) * DIN
                    + c * 64 + un * 8;
            } else {
                int v2 = u - 1024;
                int t = v2 >> 11, v = v2 & 2047, row = v >> 3, un = v & 7;
                dst = base + 16384 + t * 32768 + sw128(row * 128 + un * 16);
                src = (t ? g_rwlf : g_rwhf)
                    + (size_t)r * (DOUT * DIN) + (size_t)row * DIN + c * 64 + un * 8;
            }
            CP_ASYNC16(dst, (const char*)src);
        }
        CP_COMMIT();
    };

    float acc[2][8][4] = {};
    const int grp = lane >> 3, l7 = lane & 7;
    const int arow = (grp & 1) * 8 + l7, ac16 = (grp >> 1) * 16;
    const int brow = (grp >> 1) * 8 + l7, bc16 = (grp & 1) * 16;

    prefetch(0, 0);
    for (int c = 0; c < 4; c++) {
        if (c + 1 < 4) { prefetch(c + 1, (c + 1) & 1); CP_WAIT1(); }
        else           { CP_WAIT0(); }
        __syncthreads();
        uint32_t base = ab + (c & 1) * 81920;
        #pragma unroll
        for (int ks = 0; ks < 4; ks++) {
            int kb = ks * 32;
            uint32_t Ax[2][4];
            #pragma unroll
            for (int mf = 0; mf < 2; mf++) {
                uint32_t off = sw128((wm + mf * 16 + arow) * 128 + kb + ac16);
                ldsm4(Ax[mf][0], Ax[mf][1], Ax[mf][2], Ax[mf][3], base + off);
            }
            #pragma unroll
            for (int g = 0; g < 4; g++) {
                uint32_t off = sw128((wn + g * 16 + brow) * 128 + kb + bc16);
                uint32_t h0, h1, h2, h3, q0, q1, q2, q3;
                ldsm4(h0, h1, h2, h3, base + 16384 + off);
                ldsm4(q0, q1, q2, q3, base + 49152 + off);
                uint32_t Bh0[2] = {h0, h1}, Bh1[2] = {h2, h3};
                uint32_t Bl0[2] = {q0, q1}, Bl1[2] = {q2, q3};
                #pragma unroll
                for (int mf = 0; mf < 2; mf++) {
                    mma16816h(acc[mf][2*g],   Ax[mf], Bh0);
                    mma16816h(acc[mf][2*g+1], Ax[mf], Bh1);
                    mma16816h(acc[mf][2*g],   Ax[mf], Bl0);
                    mma16816h(acc[mf][2*g+1], Ax[mf], Bl1);
                }
            }
        }
        __syncthreads();
    }

    // ---- epilogue: bias, scale by w, transpose, store ----------------------
    #pragma unroll
    for (int nf = 0; nf < 8; nf++) {
        int c0 = wn + nf * 8 + 2 * (lane & 3);
        float b0 = rbs[c0], b1 = rbs[c0 + 1];
        #pragma unroll
        for (int mf = 0; mf < 2; mf++) {
            acc[mf][nf][0] += b0; acc[mf][nf][1] += b1;
            acc[mf][nf][2] += b0; acc[mf][nf][3] += b1;
        }
    }

    __half* thf = (__half*)abp;
    #pragma unroll
    for (int mf = 0; mf < 2; mf++)
        #pragma unroll
        for (int q = 0; q < 2; q++) {
            int row = wm + mf * 16 + q * 8 + (lane >> 2);
            float w = wsm[row];
            #pragma unroll
            for (int nf = 0; nf < 8; nf++) {
                int c0 = wn + nf * 8 + 2 * (lane & 3);
                thf[c0 * 128 + row]       = __float2half(acc[mf][nf][2 * q] * w);
                thf[(c0 + 1) * 128 + row] = __float2half(acc[mf][nf][2 * q + 1] * w);
            }
        }
    __syncthreads();

    for (int it = 0; it < 4; it++) {
        int idx = it * 512 + tid;
        int d = idx >> 3, mq = idx & 7;
        size_t go = ((size_t)br * DOUT + d) * Nn + n0 + mq * 16;
        *(uint4*)&g_wff[go]     = *(uint4*)&thf[d * 128 + mq * 16];
        *(uint4*)&g_wff[go + 8] = *(uint4*)&thf[d * 128 + mq * 16 + 8];
    }
}

// ---------------------------------------------------------------------------
// prepass: adj int32 -> fp16 {0,1}; invZ = 1/sum adj*w   [byte-exact R8/R14]
// (now independent of fw: g_w comes from w_kernel)
// ---------------------------------------------------------------------------
__global__ __launch_bounds__(256) void prepass_kernel(const int* __restrict__ adj) {
    __shared__ float ws[Nn];
    const int tid = threadIdx.x, wid = tid >> 5, lane = tid & 31;
    const int br = blockIdx.x >> 5, nb = blockIdx.x & 31;
    for (int i = tid; i < Nn; i += 256) ws[i] = g_w[br * Nn + i];
    __syncthreads();

    #pragma unroll
    for (int i = 0; i < 4; i++) {
        int n = nb * 32 + wid * 4 + i;
        const int4* arow = (const int4*)(adj + (((size_t)br << 10) + n) * Nn);
        __half* brow = g_adjh + (((size_t)br << 10) + n) * Nn;
        float z = 0.f;
        #pragma unroll
        for (int k = 0; k < 8; k++) {
            int m = k * 128 + lane * 4;
            int4 a = arow[k * 32 + lane];
            uint2 o;
            o.x = (a.x ? 0x3C00u : 0u) | ((a.y ? 0x3C00u : 0u) << 16);
            o.y = (a.z ? 0x3C00u : 0u) | ((a.w ? 0x3C00u : 0u) << 16);
            *(uint2*)(brow + m) = o;
            if (a.x) z += ws[m];
            if (a.y) z += ws[m + 1];
            if (a.z) z += ws[m + 2];
            if (a.w) z += ws[m + 3];
        }
        #pragma unroll
        for (int o = 16; o; o >>= 1) z += __shfl_xor_sync(0xffffffffu, z, o);
        if (lane == 0) g_invZ[(br << 10) + n] = 1.0f / z;
    }
}

// ---------------------------------------------------------------------------
// agg via fp16 mma.sync [byte-exact R14]
// ---------------------------------------------------------------------------
#define A_SMEM (1024 + 2 * 49152)
__global__ __launch_bounds__(256, 2) void agg_mma_kernel(float* __restrict__ out) {
    extern __shared__ char smem[];
    __shared__ float izs[Rr * 64];
    const uint32_t ab = (smem_u32(smem) + 1023) & ~1023u;
    const int tid = threadIdx.x, wid = tid >> 5, lane = tid & 31;
    const int d0 = blockIdx.x * 128;
    const int n0 = blockIdx.y * 64;
    const int b  = blockIdx.z;
    const int wm = (wid >> 2) * 32, wn = (wid & 3) * 32;

    if (tid < Rr * 64)
        izs[tid] = g_invZ[((b * Rr + (tid >> 6)) << 10) + n0 + (tid & 63)];

    auto prefetch = [&](int sc, int stage) {
        uint32_t sbase = ab + stage * 49152;
        #pragma unroll
        for (int cc = 0; cc < 2; cc++) {
            int c = sc * 2 + cc;
            int r = c >> 4, kc = c & 15, m0 = kc * 64;
            uint32_t base = sbase + cc * 24576;
            size_t brr = (size_t)(b * Rr + r);
            for (int u = tid; u < 1536; u += 256) {
                uint32_t dst;
                const __half* src;
                if (u < 512) {
                    int row = u >> 3, un = u & 7;
                    dst = base + sw128(row * 128 + un * 16);
                    src = g_adjh + (brr * Nn + n0 + row) * Nn + m0 + un * 8;
                } else {
                    int v = u - 512;
                    int row = v >> 3, un = v & 7;
                    dst = base + 8192 + sw128(row * 128 + un * 16);
                    src = g_wff + (brr * DOUT + d0 + row) * Nn + m0 + un * 8;
                }
                CP_ASYNC16(dst, (const char*)src);
            }
        }
        CP_COMMIT();
    };

    float total[2][4][4] = {};
    float acc[2][4][4] = {};
    const int grp = lane >> 3, l7 = lane & 7;
    const int arow = (grp & 1) * 8 + l7, ac16 = (grp >> 1) * 16;
    const int brow = (grp >> 1) * 8 + l7, bc16 = (grp & 1) * 16;
    const int SC = 32;

    prefetch(0, 0);
    for (int sc = 0; sc < SC; sc++) {
        if (sc + 1 < SC) { prefetch(sc + 1, (sc + 1) & 1); CP_WAIT1(); }
        else             { CP_WAIT0(); }
        __syncthreads();
        uint32_t sbase = ab + (sc & 1) * 49152;
        #pragma unroll
        for (int cc = 0; cc < 2; cc++) {
            uint32_t base = sbase + cc * 24576;
            #pragma unroll
            for (int ks = 0; ks < 4; ks++) {
                int kb = ks * 32;
                uint32_t A[2][4], Bf4[4][2];
                #pragma unroll
                for (int mf = 0; mf < 2; mf++) {
                    uint32_t off = sw128((wm + mf * 16 + arow) * 128 + kb + ac16);
                    ldsm4(A[mf][0], A[mf][1], A[mf][2], A[mf][3], base + off);
                }
                #pragma unroll
                for (int g = 0; g < 2; g++) {
                    uint32_t off = sw128((wn + g * 16 + brow) * 128 + kb + bc16);
                    uint32_t t0, t1, t2, t3;
                    ldsm4(t0, t1, t2, t3, base + 8192 + off);
                    Bf4[2*g][0] = t0; Bf4[2*g][1] = t1;
                    Bf4[2*g+1][0] = t2; Bf4[2*g+1][1] = t3;
                }
                #pragma unroll
                for (int mf = 0; mf < 2; mf++)
                    #pragma unroll
                    for (int nf = 0; nf < 4; nf++)
                        mma16816h(acc[mf][nf], A[mf], Bf4[nf]);
            }
        }
        __syncthreads();

        if ((sc & 7) == 7) {
            int r = sc >> 3;
            #pragma unroll
            for (int mf = 0; mf < 2; mf++) {
                float iz0 = izs[r * 64 + wm + mf * 16 + (lane >> 2)];
                float iz1 = izs[r * 64 + wm + mf * 16 + (lane >> 2) + 8];
                #pragma unroll
                for (int nf = 0; nf < 4; nf++) {
                    total[mf][nf][0] = fmaf(iz0, acc[mf][nf][0], total[mf][nf][0]);
                    total[mf][nf][1] = fmaf(iz0, acc[mf][nf][1], total[mf][nf][1]);
                    total[mf][nf][2] = fmaf(iz1, acc[mf][nf][2], total[mf][nf][2]);
                    total[mf][nf][3] = fmaf(iz1, acc[mf][nf][3], total[mf][nf][3]);
                    acc[mf][nf][0] = 0.f; acc[mf][nf][1] = 0.f;
                    acc[mf][nf][2] = 0.f; acc[mf][nf][3] = 0.f;
                }
            }
        }
    }

    #pragma unroll
    for (int nf = 0; nf < 4; nf++) {
        int col = d0 + wn + nf * 8 + 2 * (lane & 3);
        #pragma unroll
        for (int mf = 0; mf < 2; mf++) {
            int row = n0 + wm + mf * 16 + (lane >> 2);
            float* p0 = out + ((size_t)b * Nn + row) * DOUT + col;
            float* p1 = out + ((size_t)b * Nn + row + 8) * DOUT + col;
            p0[0] = total[mf][nf][0]; p0[1] = total[mf][nf][1];
            p1[0] = total[mf][nf][2]; p1[1] = total[mf][nf][3];
        }
    }
}

// ---------------------------------------------------------------------------
// gate: warp-per-row [byte-exact R14]
// ---------------------------------------------------------------------------
__global__ __launch_bounds__(256) void gate_kernel(
    float* __restrict__ out, const float* __restrict__ gw,
    const float* __restrict__ gb_p)
{
    const int wid = threadIdx.x >> 5, lane = threadIdx.x & 31;
    const size_t row = (size_t)blockIdx.x * 8 + wid;
    float* o = out + row * DOUT;

    float4 a0 = *(const float4*)(o + lane * 4);
    float4 a1 = *(const float4*)(o + 128 + lane * 4);
    float4 w0 = __ldg((const float4*)(gw + lane * 4));
    float4 w1 = __ldg((const float4*)(gw + 128 + lane * 4));

    float s = a0.x * w0.x + a0.y * w0.y + a0.z * w0.z + a0.w * w0.w
            + a1.x * w1.x + a1.y * w1.y + a1.z * w1.z + a1.w * w1.w;
    #pragma unroll
    for (int off = 16; off; off >>= 1) s += __shfl_xor_sync(0xffffffffu, s, off);

    float g = 1.0f / (1.0f + __expf(-(s + gb_p[0])));
    a0.x *= g; a0.y *= g; a0.z *= g; a0.w *= g;
    a1.x *= g; a1.y *= g; a1.z *= g; a1.w *= g;
    *(float4*)(o + lane * 4) = a0;
    *(float4*)(o + 128 + lane * 4) = a1;
}

// ---------------------------------------------------------------------------
extern "C" void kernel_launch(void* const* d_in, const int* in_sizes, int n_in,
                              void* d_out, int out_size)
{
    const float* x   = (const float*)d_in[0];
    const int*   adj = (const int*)  d_in[1];
    const float* rw  = (const float*)d_in[2];
    const float* rb  = (const float*)d_in[3];
    const float* aw  = (const float*)d_in[4];
    const float* gw  = (const float*)d_in[6];
    const float* gb  = (const float*)d_in[7];
    float* out = (float*)d_out;

    static cudaStream_t s2 = nullptr;
    static cudaEvent_t evA = nullptr, evB = nullptr;
    static bool init_done = false;
    if (!init_done) {
        cudaStreamCreateWithFlags(&s2, cudaStreamNonBlocking);
        cudaEventCreateWithFlags(&evA, cudaEventDisableTiming);
        cudaEventCreateWithFlags(&evB, cudaEventDisableTiming);
        cudaFuncSetAttribute(fw_kernel,
                             cudaFuncAttributeMaxDynamicSharedMemorySize, FW_SMEM);
        cudaFuncSetAttribute(agg_mma_kernel,
                             cudaFuncAttributeMaxDynamicSharedMemorySize, A_SMEM);
        init_done = true;
    }

    // w available early (linear trick): v = rw^T.awj, c = rb.awj, w = exp(x.v+c)
    vw_kernel<<<Rr, 256>>>(rw, rb, aw);
    w_kernel<<<(Bq * Nn) / 8, 256>>>(x);

    // fork: prepass (HBM-bound) runs concurrent with conv+fw (tensor-bound)
    cudaEventRecord(evA, 0);
    cudaStreamWaitEvent(s2, evA, 0);
    prepass_kernel<<<Bq * Rr * 32, 256, 0, s2>>>(adj);
    cudaEventRecord(evB, s2);

    conv_kernel<<<XB + WB, 256>>>(x, rw);
    fw_kernel<<<dim3(8, Bq * Rr), 512, FW_SMEM>>>(rb);

    // join before agg (needs g_adjh + g_invZ + g_wff)
    cudaStreamWaitEvent(0, evB, 0);
    agg_mma_kernel<<<dim3(2, 16, Bq), 256, A_SMEM>>>(out);

    gate_kernel<<<(Bq * Nn) / 8, 256>>>(out, gw, gb);
}

// round 16
// speedup vs baseline: 1.2598x; 1.2598x over previous
#include <cuda_runtime.h>
#include <cuda_fp16.h>
#include <cstdint>

#define Bq   8
#define Nn   1024
#define DIN  256
#define DOUT 256
#define Rr   4

// ------------------------- scratch globals ----------------------------------
__device__ __half g_xf[(size_t)Bq * Nn * DIN];
__device__ __half g_rwhf[(size_t)Rr * DOUT * DIN];
__device__ float  g_w[Bq * Rr * Nn];
__device__ float  g_invZ[Bq * Rr * Nn];
__device__ __half g_wff[(size_t)Bq * Rr * DOUT * Nn];      // wf^T fp16 [br][d][m]
__device__ __half g_adjh[(size_t)Bq * Rr * Nn * Nn];       // 64 MB fp16 {0,1}

// ------------------------- helpers ------------------------------------------
__device__ __forceinline__ uint32_t smem_u32(const void* p) {
    uint32_t a;
    asm("{ .reg .u64 t; cvta.to.shared.u64 t, %1; cvt.u32.u64 %0, t; }"
        : "=r"(a) : "l"(p));
    return a;
}
#define CP_ASYNC16(dst, src) asm volatile("cp.async.cg.shared.global [%0], [%1], 16;" :: "r"(dst), "l"(src))
#define CP_COMMIT()          asm volatile("cp.async.commit_group;" ::: "memory")
#define CP_WAIT1()           asm volatile("cp.async.wait_group 1;" ::: "memory")
#define CP_WAIT0()           asm volatile("cp.async.wait_group 0;" ::: "memory")

__device__ __forceinline__ uint32_t sw128(uint32_t off) {
    return off ^ ((off >> 3) & 0x70);
}
__device__ __forceinline__ void ldsm4(uint32_t& r0, uint32_t& r1,
                                      uint32_t& r2, uint32_t& r3, uint32_t a) {
    asm volatile("ldmatrix.sync.aligned.m8n8.x4.shared.b16 {%0,%1,%2,%3}, [%4];"
                 : "=r"(r0), "=r"(r1), "=r"(r2), "=r"(r3) : "r"(a));
}
__device__ __forceinline__ void mma16816h(float* c, const uint32_t* a,
                                          const uint32_t* b) {
    asm volatile("mma.sync.aligned.m16n8k16.row.col.f32.f16.f16.f32 "
        "{%0,%1,%2,%3}, {%4,%5,%6,%7}, {%8,%9}, {%0,%1,%2,%3};"
        : "+f"(c[0]), "+f"(c[1]), "+f"(c[2]), "+f"(c[3])
        : "r"(a[0]), "r"(a[1]), "r"(a[2]), "r"(a[3]), "r"(b[0]), "r"(b[1]));
}
__device__ __forceinline__ uint32_t pack_h2(__half a, __half b) {
    return (uint32_t)__half_as_ushort(a) | ((uint32_t)__half_as_ushort(b) << 16);
}

// ---------------------------------------------------------------------------
// merged conversions: blocks [0, XB) convert x; [XB, XB+WB) convert rel_w
// (both single fp16 now)
// ---------------------------------------------------------------------------
#define XB ((Bq * Nn * DIN / 4) / 256)
#define WB ((Rr * DOUT * DIN / 4) / 256)
__global__ __launch_bounds__(256) void conv_kernel(const float* __restrict__ x,
                                                   const float* __restrict__ rw) {
    if (blockIdx.x < XB) {
        size_t i = (size_t)blockIdx.x * 256 + threadIdx.x;
        float4 v = ((const float4*)x)[i];
        uint2 H;
        H.x = pack_h2(__float2half_rn(v.x), __float2half_rn(v.y));
        H.y = pack_h2(__float2half_rn(v.z), __float2half_rn(v.w));
        *(uint2*)&g_xf[4 * i] = H;
    } else {
        size_t i = (size_t)(blockIdx.x - XB) * 256 + threadIdx.x;
        float4 v = ((const float4*)rw)[i];
        uint2 H;
        H.x = pack_h2(__float2half_rn(v.x), __float2half_rn(v.y));
        H.y = pack_h2(__float2half_rn(v.z), __float2half_rn(v.w));
        *(uint2*)&g_rwhf[4 * i] = H;
    }
}

// ---------------------------------------------------------------------------
// FUSED feats+wf kernel (1-term fp16: x_h . rw_h):
//   feats[n,d] = sum_k x[n,k]*rw[d,k] + rb[d]
//   sj[n] = feats[n,:] . attn_w[256:]; w = exp(sj)
//   wf^T[d,m] = fp16(w[m] * feats[m,d]), coalesced writes
// CTA: 128n x 256d, K=256 in 4 chunks of 64, double buffered.
// 512 threads = 16 warps (4m x 4n), warp tile 32n x 64d.
// stage: A 16KB | B 32KB = 48KB, x2 = 96KB dynamic.
// ---------------------------------------------------------------------------
#define FW_SMEM (1024 + 2 * 49152)
__global__ __launch_bounds__(512, 1) void fw_kernel(
    const float* __restrict__ rb, const float* __restrict__ aw)
{
    extern __shared__ char smem[];
    __shared__ float awjs[256];
    __shared__ float rbs[256];
    __shared__ float sjred[4][128];
    __shared__ float wsm[128];
    char* abp = (char*)(((uintptr_t)smem + 1023) & ~(uintptr_t)1023);
    const uint32_t ab = (smem_u32(smem) + 1023) & ~1023u;
    const int tid = threadIdx.x, wid = tid >> 5, lane = tid & 31;
    const int n0 = blockIdx.x * 128;
    const int br = blockIdx.y, b = br >> 2, r = br & 3;
    const int wm = (wid >> 2) * 32, wn = (wid & 3) * 64;

    if (tid < 256) { awjs[tid] = aw[DOUT + tid]; rbs[tid] = rb[r * DOUT + tid]; }

    auto prefetch = [&](int c, int stage) {
        uint32_t base = ab + stage * 49152;
        for (int u = tid; u < 3072; u += 512) {
            uint32_t dst;
            const __half* src;
            if (u < 1024) {           // A: 128 rows x 64 k fp16
                int row = u >> 3, un = u & 7;
                dst = base + sw128(row * 128 + un * 16);
                src = g_xf + (size_t)b * (Nn * DIN) + (size_t)(n0 + row) * DIN
                    + c * 64 + un * 8;
            } else {                  // B: 256 rows x 64 k fp16
                int v = u - 1024;
                int row = v >> 3, un = v & 7;
                dst = base + 16384 + sw128(row * 128 + un * 16);
                src = g_rwhf + (size_t)r * (DOUT * DIN) + (size_t)row * DIN
                    + c * 64 + un * 8;
            }
            CP_ASYNC16(dst, (const char*)src);
        }
        CP_COMMIT();
    };

    float acc[2][8][4] = {};
    const int grp = lane >> 3, l7 = lane & 7;
    const int arow = (grp & 1) * 8 + l7, ac16 = (grp >> 1) * 16;
    const int brow = (grp >> 1) * 8 + l7, bc16 = (grp & 1) * 16;

    prefetch(0, 0);
    for (int c = 0; c < 4; c++) {
        if (c + 1 < 4) { prefetch(c + 1, (c + 1) & 1); CP_WAIT1(); }
        else           { CP_WAIT0(); }
        __syncthreads();
        uint32_t base = ab + (c & 1) * 49152;
        #pragma unroll
        for (int ks = 0; ks < 4; ks++) {
            int kb = ks * 32;
            uint32_t Ax[2][4];
            #pragma unroll
            for (int mf = 0; mf < 2; mf++) {
                uint32_t off = sw128((wm + mf * 16 + arow) * 128 + kb + ac16);
                ldsm4(Ax[mf][0], Ax[mf][1], Ax[mf][2], Ax[mf][3], base + off);
            }
            #pragma unroll
            for (int g = 0; g < 4; g++) {
                uint32_t off = sw128((wn + g * 16 + brow) * 128 + kb + bc16);
                uint32_t h0, h1, h2, h3;
                ldsm4(h0, h1, h2, h3, base + 16384 + off);
                uint32_t Bh0[2] = {h0, h1}, Bh1[2] = {h2, h3};
                #pragma unroll
                for (int mf = 0; mf < 2; mf++) {
                    mma16816h(acc[mf][2*g],   Ax[mf], Bh0);
                    mma16816h(acc[mf][2*g+1], Ax[mf], Bh1);
                }
            }
        }
        __syncthreads();
    }

    // ---- epilogue: bias, sj reduction, w, scale, transpose, store ----------
    #pragma unroll
    for (int nf = 0; nf < 8; nf++) {
        int c0 = wn + nf * 8 + 2 * (lane & 3);
        float b0 = rbs[c0], b1 = rbs[c0 + 1];
        #pragma unroll
        for (int mf = 0; mf < 2; mf++) {
            acc[mf][nf][0] += b0; acc[mf][nf][1] += b1;
            acc[mf][nf][2] += b0; acc[mf][nf][3] += b1;
        }
    }

    float p[2][2] = {};
    #pragma unroll
    for (int nf = 0; nf < 8; nf++) {
        int c0 = wn + nf * 8 + 2 * (lane & 3);
        float a0 = awjs[c0], a1 = awjs[c0 + 1];
        #pragma unroll
        for (int mf = 0; mf < 2; mf++) {
            p[mf][0] = fmaf(acc[mf][nf][0], a0, fmaf(acc[mf][nf][1], a1, p[mf][0]));
            p[mf][1] = fmaf(acc[mf][nf][2], a0, fmaf(acc[mf][nf][3], a1, p[mf][1]));
        }
    }
    #pragma unroll
    for (int mf = 0; mf < 2; mf++)
        #pragma unroll
        for (int q = 0; q < 2; q++) {
            p[mf][q] += __shfl_xor_sync(0xffffffffu, p[mf][q], 1);
            p[mf][q] += __shfl_xor_sync(0xffffffffu, p[mf][q], 2);
            if ((lane & 3) == 0)
                sjred[wid & 3][wm + mf * 16 + q * 8 + (lane >> 2)] = p[mf][q];
        }
    __syncthreads();

    if (tid < 128) {
        float s = sjred[0][tid] + sjred[1][tid] + sjred[2][tid] + sjred[3][tid];
        float w = __expf(s);
        wsm[tid] = w;
        g_w[br * Nn + n0 + tid] = w;
    }
    __syncthreads();

    __half* thf = (__half*)abp;      // 256 d x 128 m fp16 = 64KB (reuse stage)
    #pragma unroll
    for (int mf = 0; mf < 2; mf++)
        #pragma unroll
        for (int q = 0; q < 2; q++) {
            int row = wm + mf * 16 + q * 8 + (lane >> 2);
            float w = wsm[row];
            #pragma unroll
            for (int nf = 0; nf < 8; nf++) {
                int c0 = wn + nf * 8 + 2 * (lane & 3);
                thf[c0 * 128 + row]       = __float2half(acc[mf][nf][2 * q] * w);
                thf[(c0 + 1) * 128 + row] = __float2half(acc[mf][nf][2 * q + 1] * w);
            }
        }
    __syncthreads();

    for (int it = 0; it < 4; it++) {
        int idx = it * 512 + tid;
        int d = idx >> 3, mq = idx & 7;
        size_t go = ((size_t)br * DOUT + d) * Nn + n0 + mq * 16;
        *(uint4*)&g_wff[go]     = *(uint4*)&thf[d * 128 + mq * 16];
        *(uint4*)&g_wff[go + 8] = *(uint4*)&thf[d * 128 + mq * 16 + 8];
    }
}

// ---------------------------------------------------------------------------
// prepass: adj int32 -> fp16 {0,1}; invZ = 1/sum adj*w   [byte-exact R14]
// ---------------------------------------------------------------------------
__global__ __launch_bounds__(256) void prepass_kernel(const int* __restrict__ adj) {
    __shared__ float ws[Nn];
    const int tid = threadIdx.x, wid = tid >> 5, lane = tid & 31;
    const int br = blockIdx.x >> 5, nb = blockIdx.x & 31;
    for (int i = tid; i < Nn; i += 256) ws[i] = g_w[br * Nn + i];
    __syncthreads();

    #pragma unroll
    for (int i = 0; i < 4; i++) {
        int n = nb * 32 + wid * 4 + i;
        const int4* arow = (const int4*)(adj + (((size_t)br << 10) + n) * Nn);
        __half* brow = g_adjh + (((size_t)br << 10) + n) * Nn;
        float z = 0.f;
        #pragma unroll
        for (int k = 0; k < 8; k++) {
            int m = k * 128 + lane * 4;
            int4 a = arow[k * 32 + lane];
            uint2 o;
            o.x = (a.x ? 0x3C00u : 0u) | ((a.y ? 0x3C00u : 0u) << 16);
            o.y = (a.z ? 0x3C00u : 0u) | ((a.w ? 0x3C00u : 0u) << 16);
            *(uint2*)(brow + m) = o;
            if (a.x) z += ws[m];
            if (a.y) z += ws[m + 1];
            if (a.z) z += ws[m + 2];
            if (a.w) z += ws[m + 3];
        }
        #pragma unroll
        for (int o = 16; o; o >>= 1) z += __shfl_xor_sync(0xffffffffu, z, o);
        if (lane == 0) g_invZ[(br << 10) + n] = 1.0f / z;
    }
}

// ---------------------------------------------------------------------------
// agg via fp16 mma.sync [byte-exact R14]:
//   out[b,n,d] = sum_r invZ[r,n] * (adj_r @ wf_r^T)[n,d]
// CTA tile 64n x 128d; 32 super-chunks of K=128 (2 sub-chunks of 64).
// 8 warps 2x4, warp tile 32n x 32d. grid (2, 16, 8) = 256 CTAs, 2 CTA/SM.
// ---------------------------------------------------------------------------
#define A_SMEM (1024 + 2 * 49152)
__global__ __launch_bounds__(256, 2) void agg_mma_kernel(float* __restrict__ out) {
    extern __shared__ char smem[];
    __shared__ float izs[Rr * 64];
    const uint32_t ab = (smem_u32(smem) + 1023) & ~1023u;
    const int tid = threadIdx.x, wid = tid >> 5, lane = tid & 31;
    const int d0 = blockIdx.x * 128;
    const int n0 = blockIdx.y * 64;
    const int b  = blockIdx.z;
    const int wm = (wid >> 2) * 32, wn = (wid & 3) * 32;

    if (tid < Rr * 64)
        izs[tid] = g_invZ[((b * Rr + (tid >> 6)) << 10) + n0 + (tid & 63)];

    auto prefetch = [&](int sc, int stage) {
        uint32_t sbase = ab + stage * 49152;
        #pragma unroll
        for (int cc = 0; cc < 2; cc++) {
            int c = sc * 2 + cc;
            int r = c >> 4, kc = c & 15, m0 = kc * 64;
            uint32_t base = sbase + cc * 24576;
            size_t brr = (size_t)(b * Rr + r);
            for (int u = tid; u < 1536; u += 256) {
                uint32_t dst;
                const __half* src;
                if (u < 512) {
                    int row = u >> 3, un = u & 7;
                    dst = base + sw128(row * 128 + un * 16);
                    src = g_adjh + (brr * Nn + n0 + row) * Nn + m0 + un * 8;
                } else {
                    int v = u - 512;
                    int row = v >> 3, un = v & 7;
                    dst = base + 8192 + sw128(row * 128 + un * 16);
                    src = g_wff + (brr * DOUT + d0 + row) * Nn + m0 + un * 8;
                }
                CP_ASYNC16(dst, (const char*)src);
            }
        }
        CP_COMMIT();
    };

    float total[2][4][4] = {};
    float acc[2][4][4] = {};
    const int grp = lane >> 3, l7 = lane & 7;
    const int arow = (grp & 1) * 8 + l7, ac16 = (grp >> 1) * 16;
    const int brow = (grp >> 1) * 8 + l7, bc16 = (grp & 1) * 16;
    const int SC = 32;

    prefetch(0, 0);
    for (int sc = 0; sc < SC; sc++) {
        if (sc + 1 < SC) { prefetch(sc + 1, (sc + 1) & 1); CP_WAIT1(); }
        else             { CP_WAIT0(); }
        __syncthreads();
        uint32_t sbase = ab + (sc & 1) * 49152;
        #pragma unroll
        for (int cc = 0; cc < 2; cc++) {
            uint32_t base = sbase + cc * 24576;
            #pragma unroll
            for (int ks = 0; ks < 4; ks++) {
                int kb = ks * 32;
                uint32_t A[2][4], Bf4[4][2];
                #pragma unroll
                for (int mf = 0; mf < 2; mf++) {
                    uint32_t off = sw128((wm + mf * 16 + arow) * 128 + kb + ac16);
                    ldsm4(A[mf][0], A[mf][1], A[mf][2], A[mf][3], base + off);
                }
                #pragma unroll
                for (int g = 0; g < 2; g++) {
                    uint32_t off = sw128((wn + g * 16 + brow) * 128 + kb + bc16);
                    uint32_t t0, t1, t2, t3;
                    ldsm4(t0, t1, t2, t3, base + 8192 + off);
                    Bf4[2*g][0] = t0; Bf4[2*g][1] = t1;
                    Bf4[2*g+1][0] = t2; Bf4[2*g+1][1] = t3;
                }
                #pragma unroll
                for (int mf = 0; mf < 2; mf++)
                    #pragma unroll
                    for (int nf = 0; nf < 4; nf++)
                        mma16816h(acc[mf][nf], A[mf], Bf4[nf]);
            }
        }
        __syncthreads();

        if ((sc & 7) == 7) {             // end of relation r: fold with invZ
            int r = sc >> 3;
            #pragma unroll
            for (int mf = 0; mf < 2; mf++) {
                float iz0 = izs[r * 64 + wm + mf * 16 + (lane >> 2)];
                float iz1 = izs[r * 64 + wm + mf * 16 + (lane >> 2) + 8];
                #pragma unroll
                for (int nf = 0; nf < 4; nf++) {
                    total[mf][nf][0] = fmaf(iz0, acc[mf][nf][0], total[mf][nf][0]);
                    total[mf][nf][1] = fmaf(iz0, acc[mf][nf][1], total[mf][nf][1]);
                    total[mf][nf][2] = fmaf(iz1, acc[mf][nf][2], total[mf][nf][2]);
                    total[mf][nf][3] = fmaf(iz1, acc[mf][nf][3], total[mf][nf][3]);
                    acc[mf][nf][0] = 0.f; acc[mf][nf][1] = 0.f;
                    acc[mf][nf][2] = 0.f; acc[mf][nf][3] = 0.f;
                }
            }
        }
    }

    #pragma unroll
    for (int nf = 0; nf < 4; nf++) {
        int col = d0 + wn + nf * 8 + 2 * (lane & 3);
        #pragma unroll
        for (int mf = 0; mf < 2; mf++) {
            int row = n0 + wm + mf * 16 + (lane >> 2);
            float* p0 = out + ((size_t)b * Nn + row) * DOUT + col;
            float* p1 = out + ((size_t)b * Nn + row + 8) * DOUT + col;
            p0[0] = total[mf][nf][0]; p0[1] = total[mf][nf][1];
            p1[0] = total[mf][nf][2]; p1[1] = total[mf][nf][3];
        }
    }
}

// ---------------------------------------------------------------------------
// gate: warp-per-row [byte-exact R14]
// ---------------------------------------------------------------------------
__global__ __launch_bounds__(256) void gate_kernel(
    float* __restrict__ out, const float* __restrict__ gw,
    const float* __restrict__ gb_p)
{
    const int wid = threadIdx.x >> 5, lane = threadIdx.x & 31;
    const size_t row = (size_t)blockIdx.x * 8 + wid;
    float* o = out + row * DOUT;

    float4 a0 = *(const float4*)(o + lane * 4);
    float4 a1 = *(const float4*)(o + 128 + lane * 4);
    float4 w0 = __ldg((const float4*)(gw + lane * 4));
    float4 w1 = __ldg((const float4*)(gw + 128 + lane * 4));

    float s = a0.x * w0.x + a0.y * w0.y + a0.z * w0.z + a0.w * w0.w
            + a1.x * w1.x + a1.y * w1.y + a1.z * w1.z + a1.w * w1.w;
    #pragma unroll
    for (int off = 16; off; off >>= 1) s += __shfl_xor_sync(0xffffffffu, s, off);

    float g = 1.0f / (1.0f + __expf(-(s + gb_p[0])));
    a0.x *= g; a0.y *= g; a0.z *= g; a0.w *= g;
    a1.x *= g; a1.y *= g; a1.z *= g; a1.w *= g;
    *(float4*)(o + lane * 4) = a0;
    *(float4*)(o + 128 + lane * 4) = a1;
}

// ---------------------------------------------------------------------------
extern "C" void kernel_launch(void* const* d_in, const int* in_sizes, int n_in,
                              void* d_out, int out_size)
{
    const float* x   = (const float*)d_in[0];
    const int*   adj = (const int*)  d_in[1];
    const float* rw  = (const float*)d_in[2];
    const float* rb  = (const float*)d_in[3];
    const float* aw  = (const float*)d_in[4];
    const float* gw  = (const float*)d_in[6];
    const float* gb  = (const float*)d_in[7];
    float* out = (float*)d_out;

    static bool init_done = false;
    if (!init_done) {
        cudaFuncSetAttribute(fw_kernel,
                             cudaFuncAttributeMaxDynamicSharedMemorySize, FW_SMEM);
        cudaFuncSetAttribute(agg_mma_kernel,
                             cudaFuncAttributeMaxDynamicSharedMemorySize, A_SMEM);
        init_done = true;
    }

    conv_kernel<<<XB + WB, 256>>>(x, rw);

    fw_kernel<<<dim3(8, Bq * Rr), 512, FW_SMEM>>>(rb, aw);

    prepass_kernel<<<Bq * Rr * 32, 256>>>(adj);

    agg_mma_kernel<<<dim3(2, 16, Bq), 256, A_SMEM>>>(out);

    gate_kernel<<<(Bq * Nn) / 8, 256>>>(out, gw, gb);
}